// round 6
// baseline (speedup 1.0000x reference)
#include <cuda_runtime.h>
#include <cstdint>

// ---------------------------------------------------------------------------
// Multi-scale triplane encoder: scatter-mean of point features into 3 planes
// per scale. B=8, C=32, scales: (res=64, N=65536), (128, 32768), (256, 16384).
//
// Scatter with red.global.add.v4.f32 into channel-contiguous scratch
// (plane,b,cell,C); vectorized smem transpose (+count divide) -> (B,C,res,res).
//
// Scratch invariant: g_scr/g_cnt are ALL-ZERO between kernel_launch calls.
// The transpose restores zeros to every touched cell after reading it;
// count==0 cells skip both the read and the writeback (provably zero).
// ---------------------------------------------------------------------------

#define BATCH 8
#define CDIM 32

#define SCR_TOTAL 66060288          // 264MB scratch (same count as output)
__device__ float g_scr[SCR_TOTAL];
#define CNT_TOTAL 2064384
__device__ float g_cnt[CNT_TOTAL];

// scale bases (floats) — same for scratch and output
#define OFF0 0
#define OFF1 (3 * 8 * 32 * 64 * 64)                 //  3,145,728
#define OFF2 (OFF1 + 3 * 8 * 32 * 128 * 128)        // 15,728,640
#define CNT0 0
#define CNT1 (3 * 8 * 64 * 64)                      //  98,304
#define CNT2 (CNT1 + 3 * 8 * 128 * 128)             // 491,520

// ---------------------------------------------------------------------------
// Index math must match XLA bit-for-bit: x/C -> x*(1/C) (f32 folded), no FMA.
// ---------------------------------------------------------------------------

__device__ __forceinline__ int grid_idx(float v, float res) {
    const float R = (float)(1.0 / (double)1.10001f);
    float u = __fadd_rn(__fmul_rn(v, R), 0.5f);       // no fma contraction
    u = fminf(fmaxf(u, 0.0f), 0.99999f);
    return (int)(__fmul_rn(u, res));
}

__device__ __forceinline__ void red_v4(float* p, float a, float b, float c, float d) {
    asm volatile("red.global.add.v4.f32 [%0], {%1, %2, %3, %4};"
                 :: "l"(p), "f"(a), "f"(b), "f"(c), "f"(d)
                 : "memory");
}

template <int RES, int LOGN>
__device__ __forceinline__ void scatter_body(const float* __restrict__ f,
                                             const float* __restrict__ cd,
                                             int scr_off, int cnt_off, int gid) {
    const int R2 = RES * RES;
    int b = gid >> LOGN;

    float x = cd[gid * 3 + 0];
    float y = cd[gid * 3 + 1];
    float z = cd[gid * 3 + 2];
    int gx = grid_idx(x, (float)RES);
    int gy = grid_idx(y, (float)RES);
    int gz = grid_idx(z, (float)RES);

    int idx[3];
    idx[0] = gx + RES * gz;   // xz
    idx[1] = gx + RES * gy;   // xy
    idx[2] = gy + RES * gz;   // yz

    float4 feat[CDIM / 4];
    const float4* fv = reinterpret_cast<const float4*>(f + (size_t)gid * CDIM);
#pragma unroll
    for (int i = 0; i < CDIM / 4; i++) feat[i] = fv[i];

#pragma unroll
    for (int p = 0; p < 3; p++) {
        atomicAdd(&g_cnt[cnt_off + ((size_t)p * BATCH + b) * R2 + idx[p]], 1.0f);
        float* o = g_scr + scr_off +
                   (((size_t)p * BATCH + b) * R2 + idx[p]) * CDIM;  // 128B line
#pragma unroll
        for (int i = 0; i < CDIM / 4; i++) {
            red_v4(o + 4 * i, feat[i].x, feat[i].y, feat[i].z, feat[i].w);
        }
    }
}

// merged scatter: blocks [0,2048) scale0, [2048,3072) scale1, [3072,3584) scale2
__global__ void scatter_all_kernel(const float* __restrict__ f0, const float* __restrict__ c0,
                                   const float* __restrict__ f1, const float* __restrict__ c1,
                                   const float* __restrict__ f2, const float* __restrict__ c2) {
    int blk = blockIdx.x;
    int t = threadIdx.x;
    if (blk < 2048) {
        scatter_body<64, 16>(f0, c0, OFF0, CNT0, blk * 256 + t);
    } else if (blk < 3072) {
        scatter_body<128, 15>(f1, c1, OFF1, CNT1, (blk - 2048) * 256 + t);
    } else {
        scatter_body<256, 14>(f2, c2, OFF2, CNT2, (blk - 3072) * 256 + t);
    }
}

// ---------------------------------------------------------------------------
// Transpose (plane,b,cell,C) -> (plane,b,C,cell) + count divide, vectorized.
// 256 threads, 32 cells per block.
//  A: 8 threads LDG.128 counts -> smem; sync.
//  B: thread t: cell=t>>3, q=t&7; predicated LDG.128 of channel quad,
//     predicated STG.128 zero-writeback, 4 STS into padded tile.
//  C: 32 threads frcp counts; 8 threads zero counts; sync.
//  D: thread t: ch=t>>3, u=t&7; 4 LDS + 4 FMUL, one STG.128 of output.
// ---------------------------------------------------------------------------

template <int RES>
__device__ __forceinline__ void transpose_body(float* __restrict__ out,
                                               int scr_off, int cnt_off,
                                               int tile_idx, int b, int p) {
    const int R2 = RES * RES;
    __shared__ float tile[32][33];
    __shared__ float scnt[32];
    __shared__ float crec[32];
    int t = threadIdx.x;
    int cell0 = tile_idx * 32;

    size_t base = ((size_t)p * BATCH + b) * R2;
    float* cnt = g_cnt + cnt_off + base + cell0;
    float* src = g_scr + scr_off + (base + cell0) * CDIM;

    // A: counts -> smem
    if (t < 8) {
        float4 cv = *reinterpret_cast<const float4*>(cnt + t * 4);
        *reinterpret_cast<float4*>(&scnt[t * 4]) = cv;
    }
    __syncthreads();

    // B: predicated vector load + zero writeback + smem transpose store
    int cell = t >> 3;          // 0..31
    int q = t & 7;              // channel quad
    bool touched = (scnt[cell] != 0.0f);
    float4* sp = reinterpret_cast<float4*>(src + (size_t)cell * CDIM + q * 4);
    float4 v = make_float4(0.f, 0.f, 0.f, 0.f);
    if (touched) {
        v = *sp;
        *sp = make_float4(0.f, 0.f, 0.f, 0.f);   // restore scratch invariant
    }
    tile[cell][q * 4 + 0] = v.x;
    tile[cell][q * 4 + 1] = v.y;
    tile[cell][q * 4 + 2] = v.z;
    tile[cell][q * 4 + 3] = v.w;

    // C: reciprocals + count zero-restore
    if (t < 32) crec[t] = __frcp_rn(fmaxf(scnt[t], 1.0f));
    if (t >= 32 && t < 40) {
        *reinterpret_cast<float4*>(cnt + (t - 32) * 4) = make_float4(0.f, 0.f, 0.f, 0.f);
    }
    __syncthreads();

    // D: output — thread t: channel ch, cell quad u
    int ch = t >> 3;            // 0..31
    int u = t & 7;              // cell quad
    float4 o;
    o.x = __fmul_rn(tile[4 * u + 0][ch], crec[4 * u + 0]);
    o.y = __fmul_rn(tile[4 * u + 1][ch], crec[4 * u + 1]);
    o.z = __fmul_rn(tile[4 * u + 2][ch], crec[4 * u + 2]);
    o.w = __fmul_rn(tile[4 * u + 3][ch], crec[4 * u + 3]);
    *reinterpret_cast<float4*>(out + base * CDIM + (size_t)ch * R2 + cell0 + 4 * u) = o;
}

// merged transpose: flat grid.x decodes (scale, tile, b, p)
// scale0: 128 tiles * 24 (b,p) = 3072; scale1: 512*24=12288; scale2: 2048*24=49152
#define TR0 3072
#define TR1 (TR0 + 12288)
#define TR_TOTAL (TR1 + 49152)

__global__ void transpose_all_kernel(float* __restrict__ out) {
    int blk = blockIdx.x;
    if (blk < TR0) {
        int tile = blk & 127, bp = blk >> 7;
        transpose_body<64>(out + OFF0, OFF0, CNT0, tile, bp & 7, bp >> 3);
    } else if (blk < TR1) {
        int q = blk - TR0;
        int tile = q & 511, bp = q >> 9;
        transpose_body<128>(out + OFF1, OFF1, CNT1, tile, bp & 7, bp >> 3);
    } else {
        int q = blk - TR1;
        int tile = q & 2047, bp = q >> 11;
        transpose_body<256>(out + OFF2, OFF2, CNT2, tile, bp & 7, bp >> 3);
    }
}

// ---------------------------------------------------------------------------

extern "C" void kernel_launch(void* const* d_in, const int* in_sizes, int n_in,
                              void* d_out, int out_size) {
    // Match inputs by element count (all six are distinct).
    const float *f0 = nullptr, *f1 = nullptr, *f2 = nullptr;
    const float *c0 = nullptr, *c1 = nullptr, *c2 = nullptr;
    for (int i = 0; i < n_in; i++) {
        int s = in_sizes[i];
        const float* p = (const float*)d_in[i];
        if (s == 8 * 65536 * 32) f0 = p;
        else if (s == 8 * 32768 * 32) f1 = p;
        else if (s == 8 * 16384 * 32) f2 = p;
        else if (s == 8 * 65536 * 3) c0 = p;
        else if (s == 8 * 32768 * 3) c1 = p;
        else if (s == 8 * 16384 * 3) c2 = p;
    }

    float* out = (float*)d_out;

    // scatter all scales (scratch all-zero on entry by invariant)
    scatter_all_kernel<<<3584, 256>>>(f0, c0, f1, c1, f2, c2);

    // transpose + divide into d_out; restores scratch/count zeros
    transpose_all_kernel<<<TR_TOTAL, 256>>>(out);
}

// round 7
// speedup vs baseline: 1.5912x; 1.5912x over previous
#include <cuda_runtime.h>
#include <cstdint>

// ---------------------------------------------------------------------------
// Multi-scale triplane encoder: scatter-mean of point features into 3 planes
// per scale. B=8, C=32, scales: (res=64, N=65536), (128, 32768), (256, 16384).
//
// Scatter: red.global.add.v4.f32 into channel-contiguous scratch (p,b,cell,C).
// Transpose: dense (scale0/1) / sparse-amortized (scale2) smem transpose with
// count divide, writing (B,C,res,res). Restores the all-zero scratch invariant
// (so no zeroing pass is ever needed; __device__ globals start zeroed).
// ---------------------------------------------------------------------------

#define BATCH 8
#define CDIM 32

#define SCR_TOTAL 66060288          // 264MB scratch (same count as output)
__device__ float g_scr[SCR_TOTAL];
#define CNT_TOTAL 2064384
__device__ float g_cnt[CNT_TOTAL];

// scale bases (floats) — same for scratch and output
#define OFF0 0
#define OFF1 (3 * 8 * 32 * 64 * 64)                 //  3,145,728
#define OFF2 (OFF1 + 3 * 8 * 32 * 128 * 128)        // 15,728,640
#define CNT0 0
#define CNT1 (3 * 8 * 64 * 64)                      //  98,304
#define CNT2 (CNT1 + 3 * 8 * 128 * 128)             // 491,520

// ---------------------------------------------------------------------------
// Index math must match XLA bit-for-bit: x/C -> x*(1/C) (f32 folded), no FMA.
// ---------------------------------------------------------------------------

__device__ __forceinline__ int grid_idx(float v, float res) {
    const float R = (float)(1.0 / (double)1.10001f);
    float u = __fadd_rn(__fmul_rn(v, R), 0.5f);       // no fma contraction
    u = fminf(fmaxf(u, 0.0f), 0.99999f);
    return (int)(__fmul_rn(u, res));
}

__device__ __forceinline__ void red_v4(float* p, float a, float b, float c, float d) {
    asm volatile("red.global.add.v4.f32 [%0], {%1, %2, %3, %4};"
                 :: "l"(p), "f"(a), "f"(b), "f"(c), "f"(d)
                 : "memory");
}

template <int RES, int LOGN>
__device__ __forceinline__ void scatter_body(const float* __restrict__ f,
                                             const float* __restrict__ cd,
                                             int scr_off, int cnt_off, int gid) {
    const int R2 = RES * RES;
    int b = gid >> LOGN;

    float x = cd[gid * 3 + 0];
    float y = cd[gid * 3 + 1];
    float z = cd[gid * 3 + 2];
    int gx = grid_idx(x, (float)RES);
    int gy = grid_idx(y, (float)RES);
    int gz = grid_idx(z, (float)RES);

    int idx[3];
    idx[0] = gx + RES * gz;   // xz
    idx[1] = gx + RES * gy;   // xy
    idx[2] = gy + RES * gz;   // yz

    float4 feat[CDIM / 4];
    const float4* fv = reinterpret_cast<const float4*>(f + (size_t)gid * CDIM);
#pragma unroll
    for (int i = 0; i < CDIM / 4; i++) feat[i] = fv[i];

#pragma unroll
    for (int p = 0; p < 3; p++) {
        atomicAdd(&g_cnt[cnt_off + ((size_t)p * BATCH + b) * R2 + idx[p]], 1.0f);
        float* o = g_scr + scr_off +
                   (((size_t)p * BATCH + b) * R2 + idx[p]) * CDIM;  // 128B line
#pragma unroll
        for (int i = 0; i < CDIM / 4; i++) {
            red_v4(o + 4 * i, feat[i].x, feat[i].y, feat[i].z, feat[i].w);
        }
    }
}

// merged scatter: blocks [0,2048) scale0, [2048,3072) scale1, [3072,3584) scale2
__global__ __launch_bounds__(256)
void scatter_all_kernel(const float* __restrict__ f0, const float* __restrict__ c0,
                        const float* __restrict__ f1, const float* __restrict__ c1,
                        const float* __restrict__ f2, const float* __restrict__ c2) {
    int blk = blockIdx.x;
    int t = threadIdx.x;
    if (blk < 2048) {
        scatter_body<64, 16>(f0, c0, OFF0, CNT0, blk * 256 + t);
    } else if (blk < 3072) {
        scatter_body<128, 15>(f1, c1, OFF1, CNT1, (blk - 2048) * 256 + t);
    } else {
        scatter_body<256, 14>(f2, c2, OFF2, CNT2, (blk - 3072) * 256 + t);
    }
}

// ---------------------------------------------------------------------------
// Transpose bodies. Shared smem buffer: tile up to [128][33] + 256 floats.
// ---------------------------------------------------------------------------

#define SBUF_FLOATS (128 * 33 + 256)

// Dense 32-cell tile: NO predicates, all loads issued up front.
template <int RES>
__device__ __forceinline__ void dense32_body(float* __restrict__ out,
                                             int scr_off, int cnt_off,
                                             int tile_idx, int b, int p,
                                             float* sbuf) {
    const int R2 = RES * RES;
    float* tile = sbuf;                 // [32][33]
    float* scnt = sbuf + 32 * 33;       // [32]
    float* crec = scnt + 32;            // [32]
    int t = threadIdx.x;
    int cell0 = tile_idx * 32;

    size_t base = ((size_t)p * BATCH + b) * R2;
    float* cnt = g_cnt + cnt_off + base + cell0;
    float* src = g_scr + scr_off + (base + cell0) * CDIM;

    int cell = t >> 3, q = t & 7;
    float4* sp = reinterpret_cast<float4*>(src + (size_t)cell * CDIM + q * 4);
    float4 v = *sp;                                       // unconditional
    if (t < 8)                                            // parallel cnt load
        reinterpret_cast<float4*>(scnt)[t] =
            reinterpret_cast<const float4*>(cnt)[t];
    *sp = make_float4(0.f, 0.f, 0.f, 0.f);                // restore invariant
    tile[cell * 33 + q * 4 + 0] = v.x;
    tile[cell * 33 + q * 4 + 1] = v.y;
    tile[cell * 33 + q * 4 + 2] = v.z;
    tile[cell * 33 + q * 4 + 3] = v.w;
    __syncthreads();

    if (t < 32) crec[t] = __frcp_rn(fmaxf(scnt[t], 1.0f));
    if (t >= 32 && t < 40)
        reinterpret_cast<float4*>(cnt)[t - 32] = make_float4(0.f, 0.f, 0.f, 0.f);
    __syncthreads();

    int ch = t >> 3, u = t & 7;
    float4 o;
    o.x = __fmul_rn(tile[(4 * u + 0) * 33 + ch], crec[4 * u + 0]);
    o.y = __fmul_rn(tile[(4 * u + 1) * 33 + ch], crec[4 * u + 1]);
    o.z = __fmul_rn(tile[(4 * u + 2) * 33 + ch], crec[4 * u + 2]);
    o.w = __fmul_rn(tile[(4 * u + 3) * 33 + ch], crec[4 * u + 3]);
    *reinterpret_cast<float4*>(out + base * CDIM + (size_t)ch * R2 + cell0 + 4 * u) = o;
}

// Sparse 128-cell tile (scale2 only): one cnt round trip amortized over 4
// subtiles; 4 independent predicated LDG.128 per thread.
__device__ __forceinline__ void sparse128_body(float* __restrict__ out,
                                               int scr_off, int cnt_off,
                                               int tile_idx, int b, int p,
                                               float* sbuf) {
    const int R2 = 256 * 256;
    float* tile = sbuf;                 // [128][33]
    float* scnt = sbuf + 128 * 33;      // [128]
    float* crec = scnt + 128;           // [128]
    int t = threadIdx.x;
    int cell0 = tile_idx * 128;

    size_t base = ((size_t)p * BATCH + b) * R2;
    float* cnt = g_cnt + cnt_off + base + cell0;
    float* src = g_scr + scr_off + (base + cell0) * CDIM;

    if (t < 32)
        reinterpret_cast<float4*>(scnt)[t] =
            reinterpret_cast<const float4*>(cnt)[t];
    __syncthreads();

    int cl = t >> 3, q = t & 7;
    bool tch[4];
    float4 v[4];
    float4* sp[4];
#pragma unroll
    for (int s = 0; s < 4; s++) {
        int cell = cl + 32 * s;
        tch[s] = (scnt[cell] != 0.0f);
        sp[s] = reinterpret_cast<float4*>(src + (size_t)cell * CDIM + q * 4);
        v[s] = tch[s] ? *sp[s] : make_float4(0.f, 0.f, 0.f, 0.f);
    }
#pragma unroll
    for (int s = 0; s < 4; s++) {
        int cell = cl + 32 * s;
        if (tch[s]) *sp[s] = make_float4(0.f, 0.f, 0.f, 0.f);
        tile[cell * 33 + q * 4 + 0] = v[s].x;
        tile[cell * 33 + q * 4 + 1] = v[s].y;
        tile[cell * 33 + q * 4 + 2] = v[s].z;
        tile[cell * 33 + q * 4 + 3] = v[s].w;
    }
    if (t < 128) crec[t] = __frcp_rn(fmaxf(scnt[t], 1.0f));
    if (t >= 128 && t < 160)
        reinterpret_cast<float4*>(cnt)[t - 128] = make_float4(0.f, 0.f, 0.f, 0.f);
    __syncthreads();

    int ch = t >> 3, u = t & 7;
    float* dst = out + base * CDIM + (size_t)ch * R2 + cell0;
#pragma unroll
    for (int s = 0; s < 4; s++) {
        int c0 = 32 * s + 4 * u;
        float4 o;
        o.x = __fmul_rn(tile[(c0 + 0) * 33 + ch], crec[c0 + 0]);
        o.y = __fmul_rn(tile[(c0 + 1) * 33 + ch], crec[c0 + 1]);
        o.z = __fmul_rn(tile[(c0 + 2) * 33 + ch], crec[c0 + 2]);
        o.w = __fmul_rn(tile[(c0 + 3) * 33 + ch], crec[c0 + 3]);
        *reinterpret_cast<float4*>(dst + c0) = o;
    }
}

// merged transpose. scale2 (sparse128) first: 512 tiles * 24 (b,p) = 12288.
// scale1 (dense32): 512 * 24 = 12288.  scale0 (dense32): 128 * 24 = 3072.
#define TRA (12288)
#define TRB (TRA + 12288)
#define TR_TOTAL (TRB + 3072)

__global__ __launch_bounds__(256)
void transpose_all_kernel(float* __restrict__ out) {
    __shared__ float sbuf[SBUF_FLOATS];
    int blk = blockIdx.x;
    if (blk < TRA) {
        int tile = blk & 511, bp = blk >> 9;
        sparse128_body(out + OFF2, OFF2, CNT2, tile, bp & 7, bp >> 3, sbuf);
    } else if (blk < TRB) {
        int q = blk - TRA;
        int tile = q & 511, bp = q >> 9;
        dense32_body<128>(out + OFF1, OFF1, CNT1, tile, bp & 7, bp >> 3, sbuf);
    } else {
        int q = blk - TRB;
        int tile = q & 127, bp = q >> 7;
        dense32_body<64>(out + OFF0, OFF0, CNT0, tile, bp & 7, bp >> 3, sbuf);
    }
}

// ---------------------------------------------------------------------------

extern "C" void kernel_launch(void* const* d_in, const int* in_sizes, int n_in,
                              void* d_out, int out_size) {
    // Match inputs by element count (all six are distinct).
    const float *f0 = nullptr, *f1 = nullptr, *f2 = nullptr;
    const float *c0 = nullptr, *c1 = nullptr, *c2 = nullptr;
    for (int i = 0; i < n_in; i++) {
        int s = in_sizes[i];
        const float* p = (const float*)d_in[i];
        if (s == 8 * 65536 * 32) f0 = p;
        else if (s == 8 * 32768 * 32) f1 = p;
        else if (s == 8 * 16384 * 32) f2 = p;
        else if (s == 8 * 65536 * 3) c0 = p;
        else if (s == 8 * 32768 * 3) c1 = p;
        else if (s == 8 * 16384 * 3) c2 = p;
    }

    float* out = (float*)d_out;

    // scatter all scales (scratch all-zero on entry by invariant)
    scatter_all_kernel<<<3584, 256>>>(f0, c0, f1, c1, f2, c2);

    // transpose + divide into d_out; restores scratch/count zeros
    transpose_all_kernel<<<TR_TOTAL, 256>>>(out);
}

// round 8
// speedup vs baseline: 1.9528x; 1.2273x over previous
#include <cuda_runtime.h>
#include <cstdint>

// ---------------------------------------------------------------------------
// Multi-scale triplane encoder: scatter-mean of point features into 3 planes
// per scale. B=8, C=32, scales: (res=64, N=65536), (128, 32768), (256, 16384).
//
// Scatter: red.global.add.v4.f32 into channel-contiguous scratch (p,b,cell,C).
// Transpose: dense smem transpose (+count divide) -> (B,C,res,res), with
// MLP=4 front-batched unconditional loads and a single barrier.
// Scratch invariant: g_scr/g_cnt are ALL-ZERO between kernel_launch calls
// (restored inline: counts zeroed by their loader thread, touched scratch
// lines zeroed by predicated stores after the barrier).
// ---------------------------------------------------------------------------

#define BATCH 8
#define CDIM 32

#define SCR_TOTAL 66060288          // 264MB scratch (same count as output)
__device__ __align__(16) float g_scr[SCR_TOTAL];
#define CNT_TOTAL 2064384
__device__ __align__(16) float g_cnt[CNT_TOTAL];

// scale bases (floats) — same for scratch and output
#define OFF0 0
#define OFF1 (3 * 8 * 32 * 64 * 64)                 //  3,145,728
#define OFF2 (OFF1 + 3 * 8 * 32 * 128 * 128)        // 15,728,640
#define CNT0 0
#define CNT1 (3 * 8 * 64 * 64)                      //  98,304
#define CNT2 (CNT1 + 3 * 8 * 128 * 128)             // 491,520

// ---------------------------------------------------------------------------
// Index math must match XLA bit-for-bit: x/C -> x*(1/C) (f32 folded), no FMA.
// ---------------------------------------------------------------------------

__device__ __forceinline__ int grid_idx(float v, float res) {
    const float R = (float)(1.0 / (double)1.10001f);
    float u = __fadd_rn(__fmul_rn(v, R), 0.5f);       // no fma contraction
    u = fminf(fmaxf(u, 0.0f), 0.99999f);
    return (int)(__fmul_rn(u, res));
}

__device__ __forceinline__ void red_v4(float* p, float a, float b, float c, float d) {
    asm volatile("red.global.add.v4.f32 [%0], {%1, %2, %3, %4};"
                 :: "l"(p), "f"(a), "f"(b), "f"(c), "f"(d)
                 : "memory");
}

template <int RES, int LOGN>
__device__ __forceinline__ void scatter_body(const float* __restrict__ f,
                                             const float* __restrict__ cd,
                                             int scr_off, int cnt_off, int gid) {
    const int R2 = RES * RES;
    int b = gid >> LOGN;

    float x = cd[gid * 3 + 0];
    float y = cd[gid * 3 + 1];
    float z = cd[gid * 3 + 2];
    int gx = grid_idx(x, (float)RES);
    int gy = grid_idx(y, (float)RES);
    int gz = grid_idx(z, (float)RES);

    int idx[3];
    idx[0] = gx + RES * gz;   // xz
    idx[1] = gx + RES * gy;   // xy
    idx[2] = gy + RES * gz;   // yz

    float4 feat[CDIM / 4];
    const float4* fv = reinterpret_cast<const float4*>(f + (size_t)gid * CDIM);
#pragma unroll
    for (int i = 0; i < CDIM / 4; i++) feat[i] = fv[i];

#pragma unroll
    for (int p = 0; p < 3; p++) {
        atomicAdd(&g_cnt[cnt_off + ((size_t)p * BATCH + b) * R2 + idx[p]], 1.0f);
        float* o = g_scr + scr_off +
                   (((size_t)p * BATCH + b) * R2 + idx[p]) * CDIM;  // 128B line
#pragma unroll
        for (int i = 0; i < CDIM / 4; i++) {
            red_v4(o + 4 * i, feat[i].x, feat[i].y, feat[i].z, feat[i].w);
        }
    }
}

// merged scatter: blocks [0,2048) scale0, [2048,3072) scale1, [3072,3584) scale2
__global__ __launch_bounds__(256)
void scatter_all_kernel(const float* __restrict__ f0, const float* __restrict__ c0,
                        const float* __restrict__ f1, const float* __restrict__ c1,
                        const float* __restrict__ f2, const float* __restrict__ c2) {
    int blk = blockIdx.x;
    int t = threadIdx.x;
    if (blk < 2048) {
        scatter_body<64, 16>(f0, c0, OFF0, CNT0, blk * 256 + t);
    } else if (blk < 3072) {
        scatter_body<128, 15>(f1, c1, OFF1, CNT1, (blk - 2048) * 256 + t);
    } else {
        scatter_body<256, 14>(f2, c2, OFF2, CNT2, (blk - 3072) * 256 + t);
    }
}

// ---------------------------------------------------------------------------
// Transpose (p,b,cell,C) -> (p,b,C,cell) + count divide. Block (32,8).
//  - 4 independent scalar LDGs issued FIRST (MLP=4), unconditional.
//  - ty==0 warp: load counts, zero them (same-thread order), frcp -> smem.
//  - ONE __syncthreads.
//  - predicated zero-restore of touched scratch lines (off load path).
//  - output: 4 coalesced scalar stores per thread, multiply by reciprocal.
// ---------------------------------------------------------------------------

template <int RES>
__device__ __forceinline__ void dense_body(float* __restrict__ out,
                                           int scr_off, int cnt_off,
                                           int tile_idx, int b, int p) {
    const int R2 = RES * RES;
    __shared__ float tile[32][33];
    __shared__ float scnt[32];
    __shared__ float crec[32];
    int tx = threadIdx.x, ty = threadIdx.y;
    int cell0 = tile_idx * 32;

    size_t base = ((size_t)p * BATCH + b) * R2;
    float* cnt = g_cnt + cnt_off + base + cell0;
    float* src = g_scr + scr_off + (base + cell0) * CDIM;

    // front-batched independent loads
    float v[4];
#pragma unroll
    for (int k = 0; k < 4; k++) v[k] = src[(size_t)(ty + 8 * k) * CDIM + tx];

    if (ty == 0) {
        float c = cnt[tx];
        cnt[tx] = 0.0f;                       // restore count invariant
        scnt[tx] = c;
        crec[tx] = __frcp_rn(fmaxf(c, 1.0f));
    }

#pragma unroll
    for (int k = 0; k < 4; k++) tile[ty + 8 * k][tx] = v[k];
    __syncthreads();

    // predicated zero-restore of touched lines (fire-and-forget)
#pragma unroll
    for (int k = 0; k < 4; k++) {
        int row = ty + 8 * k;
        if (scnt[row] != 0.0f) src[(size_t)row * CDIM + tx] = 0.0f;
    }

    float* dst = out + base * CDIM + cell0;
    float r = crec[tx];
#pragma unroll
    for (int k = 0; k < 4; k++) {
        int ch = ty + 8 * k;
        dst[(size_t)ch * R2 + tx] = __fmul_rn(tile[tx][ch], r);
    }
}

// merged transpose: flat grid decodes (scale, tile, b, p)
// scale2: 2048 tiles * 24 = 49152; scale1: 512*24 = 12288; scale0: 128*24 = 3072
#define TRA 49152
#define TRB (TRA + 12288)
#define TR_TOTAL (TRB + 3072)

__global__ __launch_bounds__(256)
void transpose_all_kernel(float* __restrict__ out) {
    int blk = blockIdx.x;
    if (blk < TRA) {
        int tile = blk & 2047, bp = blk >> 11;
        dense_body<256>(out + OFF2, OFF2, CNT2, tile, bp & 7, bp >> 3);
    } else if (blk < TRB) {
        int q = blk - TRA;
        int tile = q & 511, bp = q >> 9;
        dense_body<128>(out + OFF1, OFF1, CNT1, tile, bp & 7, bp >> 3);
    } else {
        int q = blk - TRB;
        int tile = q & 127, bp = q >> 7;
        dense_body<64>(out + OFF0, OFF0, CNT0, tile, bp & 7, bp >> 3);
    }
}

// ---------------------------------------------------------------------------

extern "C" void kernel_launch(void* const* d_in, const int* in_sizes, int n_in,
                              void* d_out, int out_size) {
    // Match inputs by element count (all six are distinct).
    const float *f0 = nullptr, *f1 = nullptr, *f2 = nullptr;
    const float *c0 = nullptr, *c1 = nullptr, *c2 = nullptr;
    for (int i = 0; i < n_in; i++) {
        int s = in_sizes[i];
        const float* p = (const float*)d_in[i];
        if (s == 8 * 65536 * 32) f0 = p;
        else if (s == 8 * 32768 * 32) f1 = p;
        else if (s == 8 * 16384 * 32) f2 = p;
        else if (s == 8 * 65536 * 3) c0 = p;
        else if (s == 8 * 32768 * 3) c1 = p;
        else if (s == 8 * 16384 * 3) c2 = p;
    }

    float* out = (float*)d_out;

    // scatter all scales (scratch all-zero on entry by invariant)
    scatter_all_kernel<<<3584, 256>>>(f0, c0, f1, c1, f2, c2);

    // transpose + divide into d_out; restores scratch/count zeros
    transpose_all_kernel<<<TR_TOTAL, dim3(32, 8)>>>(out);
}